// round 7
// baseline (speedup 1.0000x reference)
#include <cuda_runtime.h>
#include <cuda_bf16.h>
#include <cstdint>

// Problem constants
#define BB 2
#define HH 192
#define WW 192
#define CC 192
#define WS 16
#define SHIFT 8
#define NH 6
#define HD 32
#define NTOK 256          // tokens per window
#define NWSIDE 12         // windows per side
#define NWB 144           // windows per batch
#define NWIN 288          // total windows
#define QK_SCALE 0.17677669529663687f  // 32^-0.5

typedef unsigned long long u64;

// ---- packed fp32x2 helpers (sm_103a FFMA2 path; ptxas never emits these from C++) ----
__device__ __forceinline__ u64 ffma2(u64 a, u64 b, u64 c) {
    u64 d; asm("fma.rn.f32x2 %0, %1, %2, %3;" : "=l"(d) : "l"(a), "l"(b), "l"(c)); return d;
}
__device__ __forceinline__ u64 fmul2(u64 a, u64 b) {
    u64 d; asm("mul.rn.f32x2 %0, %1, %2;" : "=l"(d) : "l"(a), "l"(b)); return d;
}
__device__ __forceinline__ u64 fadd2(u64 a, u64 b) {
    u64 d; asm("add.rn.f32x2 %0, %1, %2;" : "=l"(d) : "l"(a), "l"(b)); return d;
}
__device__ __forceinline__ u64 pack2(float lo, float hi) {
    u64 r; asm("mov.b64 %0, {%1, %2};" : "=l"(r) : "f"(lo), "f"(hi)); return r;
}
__device__ __forceinline__ float2 unpack2(u64 v) {
    float2 f; asm("mov.b64 {%0, %1}, %2;" : "=f"(f.x), "=f"(f.y) : "l"(v)); return f;
}

// Scratch (static __device__ globals: allowed, allocated at module load)
__device__ float g_cth[NWIN * NTOK];
__device__ float g_ctv[NWIN * NTOK];
__device__ float g_ow[(size_t)NWIN * NTOK * CC];   // attention output before projection (56.6 MB)

__device__ __forceinline__ int wrapH(int hs) { int h = hs + SHIFT; return (h >= HH) ? h - HH : h; }

// ---------------------------------------------------------------------------
// Kernel 1: per-window geo cumulative tables cth/ctv (unchanged; 52us, not hot)
// ---------------------------------------------------------------------------
__global__ void __launch_bounds__(256) geo_kernel(const float* __restrict__ x,
                                                  const float* __restrict__ geo_sigma) {
    int win = blockIdx.x;
    int b = win / NWB, wr = (win % NWB) / NWSIDE, wc = win % NWSIDE;
    int tid = threadIdx.x;

    __shared__ float dh[16][16];   // dh[r][j], j<15
    __shared__ float dv[16][16];   // dv[i][c], i<15

    float sigma = fabsf(geo_sigma[0]);

    for (int p = tid; p < 480; p += 256) {
        int r0, c0, r1, c1; bool isH = (p < 240);
        if (isH) { int r = p / 15, j = p % 15; r0 = r; c0 = j; r1 = r; c1 = j + 1; }
        else     { int pp = p - 240; int i = pp / 16, c = pp % 16; r0 = i; c0 = c; r1 = i + 1; c1 = c; }
        int h0 = wrapH(wr * WS + r0), w0 = wrapH(wc * WS + c0);
        int h1 = wrapH(wr * WS + r1), w1 = wrapH(wc * WS + c1);
        const float* a  = x + ((size_t)((b * HH + h0) * WW + w0)) * CC;
        const float* bb = x + ((size_t)((b * HH + h1) * WW + w1)) * CC;
        float s = 0.f;
        #pragma unroll 4
        for (int ch = 0; ch < CC; ch += 4) {
            float4 av = *(const float4*)(a + ch);
            float4 bv = *(const float4*)(bb + ch);
            s += fabsf(bv.x - av.x) + fabsf(bv.y - av.y) + fabsf(bv.z - av.z) + fabsf(bv.w - av.w);
        }
        if (isH) dh[r0][c0] = s; else dv[r0][c0] = s;
    }
    __syncthreads();

    if (tid < 16) {                     // horizontal cumsum: cth[r][c]
        int r = tid; float acc = 0.f;
        g_cth[win * NTOK + r * 16 + 0] = 0.f;
        for (int c = 1; c < 16; c++) {
            acc += 1.f + sigma * dh[r][c - 1];
            g_cth[win * NTOK + r * 16 + c] = acc;
        }
    } else if (tid < 32) {              // vertical cumsum: ctv[r][c]
        int c = tid - 16; float acc = 0.f;
        g_ctv[win * NTOK + 0 * 16 + c] = 0.f;
        for (int r = 1; r < 16; r++) {
            acc += 1.f + sigma * dv[r - 1][c];
            g_ctv[win * NTOK + r * 16 + c] = acc;
        }
    }
}

// ---------------------------------------------------------------------------
// Kernel 2: attention per (window, head); one thread = one query row.
// Phase-split mainloop: 16-key chunks; phase 1 = 16 independent dot+bias+exp
// chains (ILP hides MUFU/LDS latency), phase 2 = 16 independent AV updates.
// Chunk-constant rk -> rpb/geo LDS use compile-time immediate offsets.
// ---------------------------------------------------------------------------
#define SMEM2_FLOATS (8192 + 8192 + 964 + 256 + 256 + 256)
#define SMEM2_BYTES  (SMEM2_FLOATS * 4)

template<bool MIXED>
__device__ __forceinline__ void attn_mainloop(
    const float* __restrict__ K_sh, const float* __restrict__ V_sh,
    const float* __restrict__ rpb_sh, const float* __restrict__ cth_sh,
    const float* __restrict__ ctv_sh, const int* __restrict__ reg_sh,
    const u64* q2, u64* acc2, float& l,
    float cthq, float gsc, int qhi, int rq, int cq, int myreg)
{
    #pragma unroll 1
    for (int k0 = 0; k0 < NTOK; k0 += 16) {
        int rk = k0 >> 4;
        int rowbase = (rq - rk + 15) * 31 + cq + 15;
        float pbuf[16];

        // Phase 1: 16 independent score chains
        #pragma unroll
        for (int u = 0; u < 16; u++) {
            int k = k0 + u;
            const ulonglong2* kr = (const ulonglong2*)(K_sh + (k << 5));
            u64 da = 0ull, db = 0ull;
            #pragma unroll
            for (int d = 0; d < 8; d++) {
                ulonglong2 kv = kr[d];
                da = ffma2(q2[2 * d + 0], kv.x, da);
                db = ffma2(q2[2 * d + 1], kv.y, db);
            }
            float2 ds = unpack2(fadd2(da, db));
            float dot = ds.x + ds.y;
            float geo = fabsf(cth_sh[qhi + u] - cthq)
                      + fabsf(ctv_sh[k] - ctv_sh[qhi + u]);
            float s = fmaf(-gsc, geo, dot + rpb_sh[rowbase - u]);
            if (MIXED) s += (myreg == reg_sh[k]) ? 0.f : -100.f;
            pbuf[u] = __expf(s);
        }

        // Pairwise partial sum of p (short dependency tree)
        float l0 = 0.f, l1 = 0.f;
        #pragma unroll
        for (int u = 0; u < 16; u += 2) { l0 += pbuf[u]; l1 += pbuf[u + 1]; }
        l += l0 + l1;

        // Phase 2: 16 independent rank-1 AV updates
        #pragma unroll
        for (int u = 0; u < 16; u++) {
            u64 p2v = pack2(pbuf[u], pbuf[u]);
            const ulonglong2* vr = (const ulonglong2*)(V_sh + ((k0 + u) << 5));
            #pragma unroll
            for (int d = 0; d < 8; d++) {
                ulonglong2 vv = vr[d];
                acc2[2 * d + 0] = ffma2(p2v, vv.x, acc2[2 * d + 0]);
                acc2[2 * d + 1] = ffma2(p2v, vv.y, acc2[2 * d + 1]);
            }
        }
    }
}

__global__ void __launch_bounds__(256, 2) attn_kernel(const float* __restrict__ qkv,
                                                      const float* __restrict__ rpb_table,
                                                      const float* __restrict__ geo_scale) {
    extern __shared__ float smem[];
    float* K_sh   = smem;                 // [256][32]
    float* V_sh   = K_sh + 8192;          // [256][32]
    float* rpb_sh = V_sh + 8192;          // [961] (pad 964)
    float* cth_sh = rpb_sh + 964;         // [256]
    float* ctv_sh = cth_sh + 256;         // [256]
    int*   reg_sh = (int*)(ctv_sh + 256); // [256]

    int win = blockIdx.x, head = blockIdx.y;
    int b = win / NWB, wr = (win % NWB) / NWSIDE, wc = win % NWSIDE;
    int q = threadIdx.x;
    int i = q >> 4, j = q & 15;
    int hs = wr * WS + i, ws = wc * WS + j;      // shifted-image coords
    int h = wrapH(hs), w = wrapH(ws);            // original coords

    const float* base = qkv + ((size_t)((b * HH + h) * WW + w)) * (3 * CC) + head * HD;

    // q packed as 16 fp32x2 pairs (d, d+1)
    u64 q2[16];
    #pragma unroll
    for (int d = 0; d < 8; d++) {
        float4 qv = *(const float4*)(base + d * 4);
        q2[2 * d + 0] = pack2(qv.x * QK_SCALE, qv.y * QK_SCALE);
        q2[2 * d + 1] = pack2(qv.z * QK_SCALE, qv.w * QK_SCALE);
        *(float4*)(K_sh + q * HD + d * 4) = *(const float4*)(base + CC + d * 4);
        *(float4*)(V_sh + q * HD + d * 4) = *(const float4*)(base + 2 * CC + d * 4);
    }
    for (int t = q; t < 961; t += 256) rpb_sh[t] = rpb_table[t * NH + head];
    cth_sh[q] = g_cth[win * NTOK + q];
    ctv_sh[q] = g_ctv[win * NTOK + q];
    {   // shift-mask region id (on shifted coords)
        int rh = (hs < HH - WS) ? 0 : ((hs < HH - SHIFT) ? 1 : 2);
        int rw = (ws < WW - WS) ? 0 : ((ws < WW - SHIFT) ? 1 : 2);
        reg_sh[q] = rh * 3 + rw;
    }
    __syncthreads();

    float gsc  = geo_scale[head];
    float cthq = cth_sh[q];
    int myreg  = reg_sh[q];
    int qhi = q & 0xF0;
    int rq = q >> 4, cq = q & 15;

    u64 acc2[16];
    #pragma unroll
    for (int d = 0; d < 16; d++) acc2[d] = 0ull;
    float l = 0.f;

    // 121/144 windows have a uniform shift-mask region -> mask-free mainloop.
    if (wr == NWSIDE - 1 || wc == NWSIDE - 1) {
        attn_mainloop<true >(K_sh, V_sh, rpb_sh, cth_sh, ctv_sh, reg_sh,
                             q2, acc2, l, cthq, gsc, qhi, rq, cq, myreg);
    } else {
        attn_mainloop<false>(K_sh, V_sh, rpb_sh, cth_sh, ctv_sh, reg_sh,
                             q2, acc2, l, cthq, gsc, qhi, rq, cq, myreg);
    }

    float inv = 1.f / l;
    u64 inv2 = pack2(inv, inv);
    ulonglong2* op = (ulonglong2*)(g_ow + (size_t)win * (NTOK * CC) + q * CC + head * HD);
    #pragma unroll
    for (int d = 0; d < 8; d++) {
        ulonglong2 r;
        r.x = fmul2(acc2[2 * d + 0], inv2);
        r.y = fmul2(acc2[2 * d + 1], inv2);
        op[d] = r;
    }
}

// ---------------------------------------------------------------------------
// Kernel 3: projection (out_win @ proj_w.T + b) + window reverse + roll-back
// Block = 64 tokens; thread = 4 tokens x 12 output channels, fp32x2-packed.
// ---------------------------------------------------------------------------
__global__ void __launch_bounds__(256) proj_kernel(const float* __restrict__ proj_w,
                                                   const float* __restrict__ proj_b,
                                                   float* __restrict__ out) {
    __shared__ float w_sh[32 * 196];   // [kk][cout], pad 196 (16B-aligned rows)
    __shared__ float a_sh[64 * 33];    // [tok][kk], pad 33

    int blk = blockIdx.x, t = threadIdx.x;
    int tok0 = blk * 64;
    int tokl = (t & 15) * 4;
    int cob  = (t >> 4) * 12;

    u64 acc2[24];                      // [tok 0..3][pair 0..5] of 12 outputs
    #pragma unroll
    for (int e = 0; e < 24; e++) acc2[e] = 0ull;

    for (int k0 = 0; k0 < CC; k0 += 32) {
        for (int e = t; e < 2048; e += 256) {
            int tk = e >> 5, kk = e & 31;
            a_sh[tk * 33 + kk] = g_ow[(size_t)(tok0 + tk) * CC + k0 + kk];
        }
        {
            int kk = t & 31;
            for (int co = t >> 5; co < CC; co += 8)
                w_sh[kk * 196 + co] = proj_w[co * CC + k0 + kk];
        }
        __syncthreads();

        #pragma unroll 4
        for (int kk = 0; kk < 32; kk++) {
            u64 ap[4];
            #pragma unroll
            for (int t4 = 0; t4 < 4; t4++) {
                float a = a_sh[(tokl + t4) * 33 + kk];
                ap[t4] = pack2(a, a);
            }
            const ulonglong2* wp = (const ulonglong2*)(w_sh + kk * 196 + cob);
            #pragma unroll
            for (int o2 = 0; o2 < 3; o2++) {
                ulonglong2 wv = wp[o2];
                #pragma unroll
                for (int t4 = 0; t4 < 4; t4++) {
                    acc2[t4 * 6 + o2 * 2 + 0] = ffma2(ap[t4], wv.x, acc2[t4 * 6 + o2 * 2 + 0]);
                    acc2[t4 * 6 + o2 * 2 + 1] = ffma2(ap[t4], wv.y, acc2[t4 * 6 + o2 * 2 + 1]);
                }
            }
        }
        __syncthreads();
    }

    // bias (cob is a multiple of 12 -> 48B offset, 16B aligned)
    const ulonglong2* bp = (const ulonglong2*)(proj_b + cob);
    ulonglong2 bv0 = bp[0], bv1 = bp[1], bv2 = bp[2];
    u64 bb2[6] = { bv0.x, bv0.y, bv1.x, bv1.y, bv2.x, bv2.y };

    #pragma unroll
    for (int ii = 0; ii < 4; ii++) {
        int g = tok0 + tokl + ii;
        int win = g >> 8, tt = g & 255;
        int b = win / NWB, wr = (win % NWB) / NWSIDE, wc = win % NWSIDE;
        int i = tt >> 4, jj = tt & 15;
        int h = wrapH(wr * WS + i), w = wrapH(wc * WS + jj);
        ulonglong2* op = (ulonglong2*)(out + ((size_t)b * (HH * WW) + h * WW + w) * CC + cob);
        #pragma unroll
        for (int o2 = 0; o2 < 3; o2++) {
            ulonglong2 r;
            r.x = fadd2(acc2[ii * 6 + o2 * 2 + 0], bb2[o2 * 2 + 0]);
            r.y = fadd2(acc2[ii * 6 + o2 * 2 + 1], bb2[o2 * 2 + 1]);
            op[o2] = r;
        }
    }
}

// ---------------------------------------------------------------------------
// Launch. Input order per metadata: x, qkv, rpb_table, geo_scale, geo_sigma,
// proj_w, proj_b, rpi (unused), attn_mask (unused), window_size, shift_size,
// num_heads (unused).
// ---------------------------------------------------------------------------
extern "C" void kernel_launch(void* const* d_in, const int* in_sizes, int n_in,
                              void* d_out, int out_size) {
    const float* x        = (const float*)d_in[0];
    const float* qkv      = (const float*)d_in[1];
    const float* rpb      = (const float*)d_in[2];
    const float* gscale   = (const float*)d_in[3];
    const float* gsigma   = (const float*)d_in[4];
    const float* proj_w   = (const float*)d_in[5];
    const float* proj_b   = (const float*)d_in[6];
    float* out            = (float*)d_out;

    cudaFuncSetAttribute(attn_kernel, cudaFuncAttributeMaxDynamicSharedMemorySize, SMEM2_BYTES);

    geo_kernel<<<NWIN, 256>>>(x, gsigma);
    attn_kernel<<<dim3(NWIN, NH), 256, SMEM2_BYTES>>>(qkv, rpb, gscale);
    proj_kernel<<<(NWIN * NTOK) / 64, 256>>>(proj_w, proj_b, out);
}

// round 8
// speedup vs baseline: 1.6055x; 1.6055x over previous
#include <cuda_runtime.h>
#include <cuda_bf16.h>
#include <cstdint>

// Problem constants
#define BB 2
#define HH 192
#define WW 192
#define CC 192
#define WS 16
#define SHIFT 8
#define NH 6
#define HD 32
#define NTOK 256          // tokens per window
#define NWSIDE 12         // windows per side
#define NWB 144           // windows per batch
#define NWIN 288          // total windows
#define QK_SCALE 0.17677669529663687f  // 32^-0.5

typedef unsigned long long u64;

// ---- packed fp32x2 helpers (sm_103a FFMA2 path; ptxas never emits these from C++) ----
__device__ __forceinline__ u64 ffma2(u64 a, u64 b, u64 c) {
    u64 d; asm("fma.rn.f32x2 %0, %1, %2, %3;" : "=l"(d) : "l"(a), "l"(b), "l"(c)); return d;
}
__device__ __forceinline__ u64 fmul2(u64 a, u64 b) {
    u64 d; asm("mul.rn.f32x2 %0, %1, %2;" : "=l"(d) : "l"(a), "l"(b)); return d;
}
__device__ __forceinline__ u64 fadd2(u64 a, u64 b) {
    u64 d; asm("add.rn.f32x2 %0, %1, %2;" : "=l"(d) : "l"(a), "l"(b)); return d;
}
__device__ __forceinline__ u64 pack2(float lo, float hi) {
    u64 r; asm("mov.b64 %0, {%1, %2};" : "=l"(r) : "f"(lo), "f"(hi)); return r;
}
__device__ __forceinline__ float2 unpack2(u64 v) {
    float2 f; asm("mov.b64 {%0, %1}, %2;" : "=f"(f.x), "=f"(f.y) : "l"(v)); return f;
}

// Scratch (static __device__ globals: allowed, allocated at module load)
__device__ float g_cth[NWIN * NTOK];
__device__ float g_ctv[NWIN * NTOK];
__device__ float g_ow[(size_t)NWIN * NTOK * CC];   // attention output before projection (56.6 MB)

__device__ __forceinline__ int wrapH(int hs) { int h = hs + SHIFT; return (h >= HH) ? h - HH : h; }

// ---------------------------------------------------------------------------
// Kernel 1: per-window geo cumulative tables cth/ctv (unchanged; not hot)
// ---------------------------------------------------------------------------
__global__ void __launch_bounds__(256) geo_kernel(const float* __restrict__ x,
                                                  const float* __restrict__ geo_sigma) {
    int win = blockIdx.x;
    int b = win / NWB, wr = (win % NWB) / NWSIDE, wc = win % NWSIDE;
    int tid = threadIdx.x;

    __shared__ float dh[16][16];   // dh[r][j], j<15
    __shared__ float dv[16][16];   // dv[i][c], i<15

    float sigma = fabsf(geo_sigma[0]);

    for (int p = tid; p < 480; p += 256) {
        int r0, c0, r1, c1; bool isH = (p < 240);
        if (isH) { int r = p / 15, j = p % 15; r0 = r; c0 = j; r1 = r; c1 = j + 1; }
        else     { int pp = p - 240; int i = pp / 16, c = pp % 16; r0 = i; c0 = c; r1 = i + 1; c1 = c; }
        int h0 = wrapH(wr * WS + r0), w0 = wrapH(wc * WS + c0);
        int h1 = wrapH(wr * WS + r1), w1 = wrapH(wc * WS + c1);
        const float* a  = x + ((size_t)((b * HH + h0) * WW + w0)) * CC;
        const float* bb = x + ((size_t)((b * HH + h1) * WW + w1)) * CC;
        float s = 0.f;
        #pragma unroll 4
        for (int ch = 0; ch < CC; ch += 4) {
            float4 av = *(const float4*)(a + ch);
            float4 bv = *(const float4*)(bb + ch);
            s += fabsf(bv.x - av.x) + fabsf(bv.y - av.y) + fabsf(bv.z - av.z) + fabsf(bv.w - av.w);
        }
        if (isH) dh[r0][c0] = s; else dv[r0][c0] = s;
    }
    __syncthreads();

    if (tid < 16) {                     // horizontal cumsum: cth[r][c]
        int r = tid; float acc = 0.f;
        g_cth[win * NTOK + r * 16 + 0] = 0.f;
        for (int c = 1; c < 16; c++) {
            acc += 1.f + sigma * dh[r][c - 1];
            g_cth[win * NTOK + r * 16 + c] = acc;
        }
    } else if (tid < 32) {              // vertical cumsum: ctv[r][c]
        int c = tid - 16; float acc = 0.f;
        g_ctv[win * NTOK + 0 * 16 + c] = 0.f;
        for (int r = 1; r < 16; r++) {
            acc += 1.f + sigma * dv[r - 1][c];
            g_ctv[win * NTOK + r * 16 + c] = acc;
        }
    }
}

// ---------------------------------------------------------------------------
// Kernel 2: attention per (window, head); one thread = one query row.
// Chunk-4 phase split: 4 independent dot+bias+exp chains, then 4 AV updates.
// Chunks never cross a 16-key row -> rowbase hoisted, rpb LDS immediate-offset.
// Register budget kept < 128 so __launch_bounds__(256,2) holds without spill.
// ---------------------------------------------------------------------------
#define SMEM2_FLOATS (8192 + 8192 + 964 + 256 + 256 + 256)
#define SMEM2_BYTES  (SMEM2_FLOATS * 4)

template<bool MIXED>
__device__ __forceinline__ void attn_mainloop(
    const float* __restrict__ K_sh, const float* __restrict__ V_sh,
    const float* __restrict__ rpb_sh, const float* __restrict__ cth_sh,
    const float* __restrict__ ctv_sh, const int* __restrict__ reg_sh,
    const u64* q2, u64* acc2, float& l,
    float cthq, float gsc, int qhi, int rq, int cq, int myreg)
{
    #pragma unroll 1
    for (int k0 = 0; k0 < NTOK; k0 += 4) {
        int rk = k0 >> 4, ck0 = k0 & 15;
        int rowbase = (rq - rk + 15) * 31 + cq + 15 - ck0;
        float pbuf[4];

        // Phase 1: 4 independent score chains (ILP covers LDS + MUFU latency)
        #pragma unroll
        for (int u = 0; u < 4; u++) {
            int k = k0 + u;
            const ulonglong2* kr = (const ulonglong2*)(K_sh + (k << 5));
            u64 da = 0ull, db = 0ull;
            #pragma unroll
            for (int d = 0; d < 8; d++) {
                ulonglong2 kv = kr[d];
                da = ffma2(q2[2 * d + 0], kv.x, da);
                db = ffma2(q2[2 * d + 1], kv.y, db);
            }
            float2 ds = unpack2(fadd2(da, db));
            float dot = ds.x + ds.y;
            int gi = qhi + ck0 + u;
            float geo = fabsf(cth_sh[gi] - cthq) + fabsf(ctv_sh[k] - ctv_sh[gi]);
            float s = fmaf(-gsc, geo, dot + rpb_sh[rowbase - u]);
            if (MIXED) s += (myreg == reg_sh[k]) ? 0.f : -100.f;
            pbuf[u] = __expf(s);
        }

        l += (pbuf[0] + pbuf[1]) + (pbuf[2] + pbuf[3]);

        // Phase 2: 4 independent rank-1 AV updates (pure FFMA2 stream)
        #pragma unroll
        for (int u = 0; u < 4; u++) {
            u64 p2v = pack2(pbuf[u], pbuf[u]);
            const ulonglong2* vr = (const ulonglong2*)(V_sh + ((k0 + u) << 5));
            #pragma unroll
            for (int d = 0; d < 8; d++) {
                ulonglong2 vv = vr[d];
                acc2[2 * d + 0] = ffma2(p2v, vv.x, acc2[2 * d + 0]);
                acc2[2 * d + 1] = ffma2(p2v, vv.y, acc2[2 * d + 1]);
            }
        }
    }
}

__global__ void __launch_bounds__(256, 2) attn_kernel(const float* __restrict__ qkv,
                                                      const float* __restrict__ rpb_table,
                                                      const float* __restrict__ geo_scale) {
    extern __shared__ float smem[];
    float* K_sh   = smem;                 // [256][32]
    float* V_sh   = K_sh + 8192;          // [256][32]
    float* rpb_sh = V_sh + 8192;          // [961] (pad 964)
    float* cth_sh = rpb_sh + 964;         // [256]
    float* ctv_sh = cth_sh + 256;         // [256]
    int*   reg_sh = (int*)(ctv_sh + 256); // [256]

    int win = blockIdx.x, head = blockIdx.y;
    int b = win / NWB, wr = (win % NWB) / NWSIDE, wc = win % NWSIDE;
    int q = threadIdx.x;
    int i = q >> 4, j = q & 15;
    int hs = wr * WS + i, ws = wc * WS + j;      // shifted-image coords
    int h = wrapH(hs), w = wrapH(ws);            // original coords

    const float* base = qkv + ((size_t)((b * HH + h) * WW + w)) * (3 * CC) + head * HD;

    // q packed as 16 fp32x2 pairs (d, d+1)
    u64 q2[16];
    #pragma unroll
    for (int d = 0; d < 8; d++) {
        float4 qv = *(const float4*)(base + d * 4);
        q2[2 * d + 0] = pack2(qv.x * QK_SCALE, qv.y * QK_SCALE);
        q2[2 * d + 1] = pack2(qv.z * QK_SCALE, qv.w * QK_SCALE);
        *(float4*)(K_sh + q * HD + d * 4) = *(const float4*)(base + CC + d * 4);
        *(float4*)(V_sh + q * HD + d * 4) = *(const float4*)(base + 2 * CC + d * 4);
    }
    for (int t = q; t < 961; t += 256) rpb_sh[t] = rpb_table[t * NH + head];
    cth_sh[q] = g_cth[win * NTOK + q];
    ctv_sh[q] = g_ctv[win * NTOK + q];
    {   // shift-mask region id (on shifted coords)
        int rh = (hs < HH - WS) ? 0 : ((hs < HH - SHIFT) ? 1 : 2);
        int rw = (ws < WW - WS) ? 0 : ((ws < WW - SHIFT) ? 1 : 2);
        reg_sh[q] = rh * 3 + rw;
    }
    __syncthreads();

    float gsc  = geo_scale[head];
    float cthq = cth_sh[q];
    int myreg  = reg_sh[q];
    int qhi = q & 0xF0;
    int rq = q >> 4, cq = q & 15;

    u64 acc2[16];
    #pragma unroll
    for (int d = 0; d < 16; d++) acc2[d] = 0ull;
    float l = 0.f;

    // 121/144 windows have a uniform shift-mask region -> mask-free mainloop.
    if (wr == NWSIDE - 1 || wc == NWSIDE - 1) {
        attn_mainloop<true >(K_sh, V_sh, rpb_sh, cth_sh, ctv_sh, reg_sh,
                             q2, acc2, l, cthq, gsc, qhi, rq, cq, myreg);
    } else {
        attn_mainloop<false>(K_sh, V_sh, rpb_sh, cth_sh, ctv_sh, reg_sh,
                             q2, acc2, l, cthq, gsc, qhi, rq, cq, myreg);
    }

    float inv = 1.f / l;
    u64 inv2 = pack2(inv, inv);
    ulonglong2* op = (ulonglong2*)(g_ow + (size_t)win * (NTOK * CC) + q * CC + head * HD);
    #pragma unroll
    for (int d = 0; d < 8; d++) {
        ulonglong2 r;
        r.x = fmul2(acc2[2 * d + 0], inv2);
        r.y = fmul2(acc2[2 * d + 1], inv2);
        op[d] = r;
    }
}

// ---------------------------------------------------------------------------
// Kernel 3: projection (out_win @ proj_w.T + b) + window reverse + roll-back
// Block = 64 tokens; thread = 4 tokens x 12 output channels, fp32x2-packed.
// ---------------------------------------------------------------------------
__global__ void __launch_bounds__(256) proj_kernel(const float* __restrict__ proj_w,
                                                   const float* __restrict__ proj_b,
                                                   float* __restrict__ out) {
    __shared__ float w_sh[32 * 196];   // [kk][cout], pad 196 (16B-aligned rows)
    __shared__ float a_sh[64 * 33];    // [tok][kk], pad 33

    int blk = blockIdx.x, t = threadIdx.x;
    int tok0 = blk * 64;
    int tokl = (t & 15) * 4;
    int cob  = (t >> 4) * 12;

    u64 acc2[24];                      // [tok 0..3][pair 0..5] of 12 outputs
    #pragma unroll
    for (int e = 0; e < 24; e++) acc2[e] = 0ull;

    for (int k0 = 0; k0 < CC; k0 += 32) {
        for (int e = t; e < 2048; e += 256) {
            int tk = e >> 5, kk = e & 31;
            a_sh[tk * 33 + kk] = g_ow[(size_t)(tok0 + tk) * CC + k0 + kk];
        }
        {
            int kk = t & 31;
            for (int co = t >> 5; co < CC; co += 8)
                w_sh[kk * 196 + co] = proj_w[co * CC + k0 + kk];
        }
        __syncthreads();

        #pragma unroll 4
        for (int kk = 0; kk < 32; kk++) {
            u64 ap[4];
            #pragma unroll
            for (int t4 = 0; t4 < 4; t4++) {
                float a = a_sh[(tokl + t4) * 33 + kk];
                ap[t4] = pack2(a, a);
            }
            const ulonglong2* wp = (const ulonglong2*)(w_sh + kk * 196 + cob);
            #pragma unroll
            for (int o2 = 0; o2 < 3; o2++) {
                ulonglong2 wv = wp[o2];
                #pragma unroll
                for (int t4 = 0; t4 < 4; t4++) {
                    acc2[t4 * 6 + o2 * 2 + 0] = ffma2(ap[t4], wv.x, acc2[t4 * 6 + o2 * 2 + 0]);
                    acc2[t4 * 6 + o2 * 2 + 1] = ffma2(ap[t4], wv.y, acc2[t4 * 6 + o2 * 2 + 1]);
                }
            }
        }
        __syncthreads();
    }

    // bias (cob is a multiple of 12 -> 48B offset, 16B aligned)
    const ulonglong2* bp = (const ulonglong2*)(proj_b + cob);
    ulonglong2 bv0 = bp[0], bv1 = bp[1], bv2 = bp[2];
    u64 bb2[6] = { bv0.x, bv0.y, bv1.x, bv1.y, bv2.x, bv2.y };

    #pragma unroll
    for (int ii = 0; ii < 4; ii++) {
        int g = tok0 + tokl + ii;
        int win = g >> 8, tt = g & 255;
        int b = win / NWB, wr = (win % NWB) / NWSIDE, wc = win % NWSIDE;
        int i = tt >> 4, jj = tt & 15;
        int h = wrapH(wr * WS + i), w = wrapH(wc * WS + jj);
        ulonglong2* op = (ulonglong2*)(out + ((size_t)b * (HH * WW) + h * WW + w) * CC + cob);
        #pragma unroll
        for (int o2 = 0; o2 < 3; o2++) {
            ulonglong2 r;
            r.x = fadd2(acc2[ii * 6 + o2 * 2 + 0], bb2[o2 * 2 + 0]);
            r.y = fadd2(acc2[ii * 6 + o2 * 2 + 1], bb2[o2 * 2 + 1]);
            op[o2] = r;
        }
    }
}

// ---------------------------------------------------------------------------
// Launch. Input order per metadata: x, qkv, rpb_table, geo_scale, geo_sigma,
// proj_w, proj_b, rpi (unused), attn_mask (unused), window_size, shift_size,
// num_heads (unused).
// ---------------------------------------------------------------------------
extern "C" void kernel_launch(void* const* d_in, const int* in_sizes, int n_in,
                              void* d_out, int out_size) {
    const float* x        = (const float*)d_in[0];
    const float* qkv      = (const float*)d_in[1];
    const float* rpb      = (const float*)d_in[2];
    const float* gscale   = (const float*)d_in[3];
    const float* gsigma   = (const float*)d_in[4];
    const float* proj_w   = (const float*)d_in[5];
    const float* proj_b   = (const float*)d_in[6];
    float* out            = (float*)d_out;

    cudaFuncSetAttribute(attn_kernel, cudaFuncAttributeMaxDynamicSharedMemorySize, SMEM2_BYTES);

    geo_kernel<<<NWIN, 256>>>(x, gsigma);
    attn_kernel<<<dim3(NWIN, NH), 256, SMEM2_BYTES>>>(qkv, rpb, gscale);
    proj_kernel<<<(NWIN * NTOK) / 64, 256>>>(proj_w, proj_b, out);
}

// round 9
// speedup vs baseline: 2.4117x; 1.5022x over previous
#include <cuda_runtime.h>
#include <cuda_bf16.h>
#include <cstdint>

// Problem constants
#define BB 2
#define HH 192
#define WW 192
#define CC 192
#define WS 16
#define SHIFT 8
#define NH 6
#define HD 32
#define NTOK 256          // tokens per window
#define NWSIDE 12         // windows per side
#define NWB 144           // windows per batch
#define NWIN 288          // total windows
#define QK_SCALE 0.17677669529663687f  // 32^-0.5

typedef unsigned long long u64;

// ---- packed fp32x2 helpers (used by proj kernel) ----
__device__ __forceinline__ u64 ffma2(u64 a, u64 b, u64 c) {
    u64 d; asm("fma.rn.f32x2 %0, %1, %2, %3;" : "=l"(d) : "l"(a), "l"(b), "l"(c)); return d;
}
__device__ __forceinline__ u64 fadd2(u64 a, u64 b) {
    u64 d; asm("add.rn.f32x2 %0, %1, %2;" : "=l"(d) : "l"(a), "l"(b)); return d;
}
__device__ __forceinline__ u64 pack2(float lo, float hi) {
    u64 r; asm("mov.b64 %0, {%1, %2};" : "=l"(r) : "f"(lo), "f"(hi)); return r;
}

// ---- mma / ldmatrix helpers ----
__device__ __forceinline__ uint32_t smem_u32(const void* p) {
    return (uint32_t)__cvta_generic_to_shared(p);
}
__device__ __forceinline__ void ldsm_x2(uint32_t& r0, uint32_t& r1, uint32_t addr) {
    asm volatile("ldmatrix.sync.aligned.m8n8.x2.shared.b16 {%0,%1}, [%2];"
                 : "=r"(r0), "=r"(r1) : "r"(addr));
}
__device__ __forceinline__ void ldsm_x2_t(uint32_t& r0, uint32_t& r1, uint32_t addr) {
    asm volatile("ldmatrix.sync.aligned.m8n8.x2.trans.shared.b16 {%0,%1}, [%2];"
                 : "=r"(r0), "=r"(r1) : "r"(addr));
}
__device__ __forceinline__ void mma_bf16(float* c, const uint32_t* a, const uint32_t* b) {
    asm volatile("mma.sync.aligned.m16n8k16.row.col.f32.bf16.bf16.f32 "
                 "{%0,%1,%2,%3},{%4,%5,%6,%7},{%8,%9},{%0,%1,%2,%3};"
                 : "+f"(c[0]), "+f"(c[1]), "+f"(c[2]), "+f"(c[3])
                 : "r"(a[0]), "r"(a[1]), "r"(a[2]), "r"(a[3]), "r"(b[0]), "r"(b[1]));
}
__device__ __forceinline__ uint32_t bf2(float x, float y) {
    __nv_bfloat162 t = __floats2bfloat162_rn(x, y);   // .x = x (low half)
    return *(uint32_t*)&t;
}
__device__ __forceinline__ void split_pack(float x, float y, uint32_t& hi, uint32_t& lo) {
    __nv_bfloat16 hx = __float2bfloat16(x), hy = __float2bfloat16(y);
    __nv_bfloat162 h2 = __halves2bfloat162(hx, hy);
    hi = *(uint32_t*)&h2;
    lo = bf2(x - __bfloat162float(hx), y - __bfloat162float(hy));
}

// Scratch (static __device__ globals)
__device__ float g_cth[NWIN * NTOK];
__device__ float g_ctv[NWIN * NTOK];
__device__ float g_ow[(size_t)NWIN * NTOK * CC];

__device__ __forceinline__ int wrapH(int hs) { int h = hs + SHIFT; return (h >= HH) ? h - HH : h; }

// ---------------------------------------------------------------------------
// Kernel 1: per-window geo cumulative tables cth/ctv (unchanged)
// ---------------------------------------------------------------------------
__global__ void __launch_bounds__(256) geo_kernel(const float* __restrict__ x,
                                                  const float* __restrict__ geo_sigma) {
    int win = blockIdx.x;
    int b = win / NWB, wr = (win % NWB) / NWSIDE, wc = win % NWSIDE;
    int tid = threadIdx.x;

    __shared__ float dh[16][16];
    __shared__ float dv[16][16];

    float sigma = fabsf(geo_sigma[0]);

    for (int p = tid; p < 480; p += 256) {
        int r0, c0, r1, c1; bool isH = (p < 240);
        if (isH) { int r = p / 15, j = p % 15; r0 = r; c0 = j; r1 = r; c1 = j + 1; }
        else     { int pp = p - 240; int i = pp / 16, c = pp % 16; r0 = i; c0 = c; r1 = i + 1; c1 = c; }
        int h0 = wrapH(wr * WS + r0), w0 = wrapH(wc * WS + c0);
        int h1 = wrapH(wr * WS + r1), w1 = wrapH(wc * WS + c1);
        const float* a  = x + ((size_t)((b * HH + h0) * WW + w0)) * CC;
        const float* bb = x + ((size_t)((b * HH + h1) * WW + w1)) * CC;
        float s = 0.f;
        #pragma unroll 4
        for (int ch = 0; ch < CC; ch += 4) {
            float4 av = *(const float4*)(a + ch);
            float4 bv = *(const float4*)(bb + ch);
            s += fabsf(bv.x - av.x) + fabsf(bv.y - av.y) + fabsf(bv.z - av.z) + fabsf(bv.w - av.w);
        }
        if (isH) dh[r0][c0] = s; else dv[r0][c0] = s;
    }
    __syncthreads();

    if (tid < 16) {
        int r = tid; float acc = 0.f;
        g_cth[win * NTOK + r * 16 + 0] = 0.f;
        for (int c = 1; c < 16; c++) {
            acc += 1.f + sigma * dh[r][c - 1];
            g_cth[win * NTOK + r * 16 + c] = acc;
        }
    } else if (tid < 32) {
        int c = tid - 16; float acc = 0.f;
        g_ctv[win * NTOK + 0 * 16 + c] = 0.f;
        for (int r = 1; r < 16; r++) {
            acc += 1.f + sigma * dv[r - 1][c];
            g_ctv[win * NTOK + r * 16 + c] = acc;
        }
    }
}

// ---------------------------------------------------------------------------
// Kernel 2: attention via mma.sync bf16 with hi/lo split (fp32-grade accuracy).
// Block = one (window, head), 8 warps; warp handles 32 q-rows.
// K/V in smem as bf16 hi/lo, row stride 40 elems (80B) -> conflict-free ldmatrix.
// ---------------------------------------------------------------------------
#define KV_STRIDE 40
#define SMEM2_BYTES (4 * 256 * KV_STRIDE * 2 + (964 + 256 + 256 + 256) * 4)

__device__ __forceinline__ const float* q_row_ptr(const float* qkv, int b, int wr, int wc,
                                                  int t, int head) {
    int i = t >> 4, j = t & 15;
    int h = wrapH(wr * WS + i), w = wrapH(wc * WS + j);
    return qkv + ((size_t)((b * HH + h) * WW + w)) * (3 * CC) + head * HD;
}

__global__ void __launch_bounds__(256) attn_kernel(const float* __restrict__ qkv,
                                                   const float* __restrict__ rpb_table,
                                                   const float* __restrict__ geo_scale) {
    extern __shared__ char smem_raw[];
    __nv_bfloat16* Kh = (__nv_bfloat16*)smem_raw;              // [256][40]
    __nv_bfloat16* Kl = Kh + 256 * KV_STRIDE;
    __nv_bfloat16* Vh = Kl + 256 * KV_STRIDE;
    __nv_bfloat16* Vl = Vh + 256 * KV_STRIDE;
    float* rpb_sh = (float*)(smem_raw + 4 * 256 * KV_STRIDE * 2);  // [961] pad 964
    float* cth_sh = rpb_sh + 964;
    float* ctv_sh = cth_sh + 256;
    int*   reg_sh = (int*)(ctv_sh + 256);

    int win = blockIdx.x, head = blockIdx.y;
    int b = win / NWB, wr = (win % NWB) / NWSIDE, wc = win % NWSIDE;
    int tid = threadIdx.x;

    // ---- fill K/V hi/lo + tables ----
    {
        int t = tid;
        int i = t >> 4, j = t & 15;
        int hs = wr * WS + i, ws = wc * WS + j;
        int h = wrapH(hs), w = wrapH(ws);
        const float* base = qkv + ((size_t)((b * HH + h) * WW + w)) * (3 * CC) + head * HD;
        const float* kp = base + CC;
        const float* vp = base + 2 * CC;
        #pragma unroll 8
        for (int d = 0; d < 32; d++) {
            float kv = kp[d];
            __nv_bfloat16 khv = __float2bfloat16(kv);
            Kh[t * KV_STRIDE + d] = khv;
            Kl[t * KV_STRIDE + d] = __float2bfloat16(kv - __bfloat162float(khv));
            float vv = vp[d];
            __nv_bfloat16 vhv = __float2bfloat16(vv);
            Vh[t * KV_STRIDE + d] = vhv;
            Vl[t * KV_STRIDE + d] = __float2bfloat16(vv - __bfloat162float(vhv));
        }
        for (int u = tid; u < 961; u += 256) rpb_sh[u] = rpb_table[u * NH + head];
        cth_sh[t] = g_cth[win * NTOK + t];
        ctv_sh[t] = g_ctv[win * NTOK + t];
        int rh  = (hs < HH - WS) ? 0 : ((hs < HH - SHIFT) ? 1 : 2);
        int rw2 = (ws < WW - WS) ? 0 : ((ws < WW - SHIFT) ? 1 : 2);
        reg_sh[t] = rh * 3 + rw2;
    }

    int warp = tid >> 5, lane = tid & 31;
    int g = lane >> 2, t4 = lane & 3;

    // ---- Q fragments straight from gmem (scale folded, hi/lo split) ----
    uint32_t qfh[2][2][4], qfl[2][2][4];
    #pragma unroll
    for (int rt = 0; rt < 2; rt++) {
        int R = warp * 32 + rt * 16;
        const float* p0 = q_row_ptr(qkv, b, wr, wc, R + g, head);
        const float* p1 = q_row_ptr(qkv, b, wr, wc, R + g + 8, head);
        #pragma unroll
        for (int ks = 0; ks < 2; ks++) {
            int kc = ks * 16 + 2 * t4;
            float2 v;
            v = *(const float2*)(p0 + kc);
            split_pack(v.x * QK_SCALE, v.y * QK_SCALE, qfh[rt][ks][0], qfl[rt][ks][0]);
            v = *(const float2*)(p1 + kc);
            split_pack(v.x * QK_SCALE, v.y * QK_SCALE, qfh[rt][ks][1], qfl[rt][ks][1]);
            v = *(const float2*)(p0 + kc + 8);
            split_pack(v.x * QK_SCALE, v.y * QK_SCALE, qfh[rt][ks][2], qfl[rt][ks][2]);
            v = *(const float2*)(p1 + kc + 8);
            split_pack(v.x * QK_SCALE, v.y * QK_SCALE, qfh[rt][ks][3], qfl[rt][ks][3]);
        }
    }
    __syncthreads();

    // ---- per-rt epilogue constants ----
    float gsc = geo_scale[head];
    float cth_q[2][2]; int myreg[2][2];
    #pragma unroll
    for (int rt = 0; rt < 2; rt++) {
        int R = warp * 32 + rt * 16;
        cth_q[rt][0] = cth_sh[R + g];     myreg[rt][0] = reg_sh[R + g];
        cth_q[rt][1] = cth_sh[R + g + 8]; myreg[rt][1] = reg_sh[R + g + 8];
    }

    float o[2][4][4];
    #pragma unroll
    for (int rt = 0; rt < 2; rt++)
        #pragma unroll
        for (int dn = 0; dn < 4; dn++)
            #pragma unroll
            for (int e = 0; e < 4; e++) o[rt][dn][e] = 0.f;
    float lsum[2][2] = {{0.f, 0.f}, {0.f, 0.f}};

    int lrow = lane & 7, lhi = (lane >> 3) & 1;

    #pragma unroll 1
    for (int T = 0; T < 8; T++) {
        int kb = T * 32;

        // K fragments (B operand of QK^T): ldmatrix non-trans on [key][k]
        uint32_t kf_h[4][2][2], kf_l[4][2][2];
        #pragma unroll
        for (int nt = 0; nt < 4; nt++) {
            int row = kb + nt * 8 + lrow;
            #pragma unroll
            for (int ks = 0; ks < 2; ks++) {
                int eoff = ks * 16 + 8 * lhi;
                ldsm_x2(kf_h[nt][ks][0], kf_h[nt][ks][1], smem_u32(&Kh[row * KV_STRIDE + eoff]));
                ldsm_x2(kf_l[nt][ks][0], kf_l[nt][ks][1], smem_u32(&Kl[row * KV_STRIDE + eoff]));
            }
        }
        // V fragments (B operand of AV): ldmatrix.trans on [key][d]
        uint32_t vf_h[4][2][2], vf_l[4][2][2];
        #pragma unroll
        for (int kt = 0; kt < 2; kt++) {
            int key = kb + kt * 16 + lrow + 8 * lhi;
            #pragma unroll
            for (int dn = 0; dn < 4; dn++) {
                ldsm_x2_t(vf_h[dn][kt][0], vf_h[dn][kt][1], smem_u32(&Vh[key * KV_STRIDE + dn * 8]));
                ldsm_x2_t(vf_l[dn][kt][0], vf_l[dn][kt][1], smem_u32(&Vl[key * KV_STRIDE + dn * 8]));
            }
        }

        // S = Qh*Kh + Qh*Kl + Ql*Kh, then bias+exp epilogue, pack P hi/lo frags
        uint32_t pf_h[2][2][4], pf_l[2][2][4];
        #pragma unroll
        for (int rt = 0; rt < 2; rt++) {
            int R = warp * 32 + rt * 16;
            int rq = warp * 2 + rt;
            #pragma unroll
            for (int nt = 0; nt < 4; nt++) {
                float c[4] = {0.f, 0.f, 0.f, 0.f};
                #pragma unroll
                for (int ks = 0; ks < 2; ks++) {
                    mma_bf16(c, qfh[rt][ks], kf_h[nt][ks]);
                    mma_bf16(c, qfh[rt][ks], kf_l[nt][ks]);
                    mma_bf16(c, qfl[rt][ks], kf_h[nt][ks]);
                }
                int rk = (kb >> 4) + (nt >> 1);
                int rowoff = (rq - rk + 15) * 31 + 15;
                int ck0 = (nt & 1) * 8 + 2 * t4;
                int k0 = kb + nt * 8 + 2 * t4;

                // element column k0  (q rows R+g and R+g+8)
                float cthgi0 = cth_sh[R + ck0];
                float ctvgi0 = ctv_sh[R + ck0];
                float ctvk0  = ctv_sh[k0];
                int   mr0    = reg_sh[k0];
                float geo00 = fabsf(cthgi0 - cth_q[rt][0]) + fabsf(ctvk0 - ctvgi0);
                float geo01 = fabsf(cthgi0 - cth_q[rt][1]) + fabsf(ctvk0 - ctvgi0);
                float s0 = fmaf(-gsc, geo00, c[0] + rpb_sh[rowoff + g - ck0])
                         + ((myreg[rt][0] == mr0) ? 0.f : -100.f);
                float s2 = fmaf(-gsc, geo01, c[2] + rpb_sh[rowoff + g + 8 - ck0])
                         + ((myreg[rt][1] == mr0) ? 0.f : -100.f);

                // element column k0+1
                float cthgi1 = cth_sh[R + ck0 + 1];
                float ctvgi1 = ctv_sh[R + ck0 + 1];
                float ctvk1  = ctv_sh[k0 + 1];
                int   mr1    = reg_sh[k0 + 1];
                float geo10 = fabsf(cthgi1 - cth_q[rt][0]) + fabsf(ctvk1 - ctvgi1);
                float geo11 = fabsf(cthgi1 - cth_q[rt][1]) + fabsf(ctvk1 - ctvgi1);
                float s1 = fmaf(-gsc, geo10, c[1] + rpb_sh[rowoff + g - ck0 - 1])
                         + ((myreg[rt][0] == mr1) ? 0.f : -100.f);
                float s3 = fmaf(-gsc, geo11, c[3] + rpb_sh[rowoff + g + 8 - ck0 - 1])
                         + ((myreg[rt][1] == mr1) ? 0.f : -100.f);

                float p0 = __expf(s0), p1 = __expf(s1);
                float p2 = __expf(s2), p3 = __expf(s3);
                lsum[rt][0] += p0 + p1;
                lsum[rt][1] += p2 + p3;

                // hi/lo split + pack into A-fragments for AV (C->A identity)
                __nv_bfloat16 h0 = __float2bfloat16(p0), h1 = __float2bfloat16(p1);
                __nv_bfloat16 h2 = __float2bfloat16(p2), h3 = __float2bfloat16(p3);
                int kt = nt >> 1, off = (nt & 1) * 2;
                __nv_bfloat162 hp01 = __halves2bfloat162(h0, h1);
                __nv_bfloat162 hp23 = __halves2bfloat162(h2, h3);
                pf_h[rt][kt][off]     = *(uint32_t*)&hp01;
                pf_h[rt][kt][off + 1] = *(uint32_t*)&hp23;
                pf_l[rt][kt][off]     = bf2(p0 - __bfloat162float(h0), p1 - __bfloat162float(h1));
                pf_l[rt][kt][off + 1] = bf2(p2 - __bfloat162float(h2), p3 - __bfloat162float(h3));
            }
        }

        // O += Ph*Vh + Ph*Vl + Pl*Vh
        #pragma unroll
        for (int rt = 0; rt < 2; rt++)
            #pragma unroll
            for (int dn = 0; dn < 4; dn++)
                #pragma unroll
                for (int kt = 0; kt < 2; kt++) {
                    mma_bf16(o[rt][dn], pf_h[rt][kt], vf_h[dn][kt]);
                    mma_bf16(o[rt][dn], pf_h[rt][kt], vf_l[dn][kt]);
                    mma_bf16(o[rt][dn], pf_l[rt][kt], vf_h[dn][kt]);
                }
    }

    // reduce l across the 4 threads sharing each row (lane%4 group)
    #pragma unroll
    for (int rt = 0; rt < 2; rt++)
        #pragma unroll
        for (int r = 0; r < 2; r++) {
            float v = lsum[rt][r];
            v += __shfl_xor_sync(0xFFFFFFFF, v, 1);
            v += __shfl_xor_sync(0xFFFFFFFF, v, 2);
            lsum[rt][r] = v;
        }

    // normalize + store
    #pragma unroll
    for (int rt = 0; rt < 2; rt++) {
        int R = warp * 32 + rt * 16;
        float inv0 = 1.f / lsum[rt][0];
        float inv1 = 1.f / lsum[rt][1];
        float* b0 = g_ow + (size_t)win * (NTOK * CC) + (R + g) * CC + head * HD + 2 * t4;
        float* b1 = g_ow + (size_t)win * (NTOK * CC) + (R + g + 8) * CC + head * HD + 2 * t4;
        #pragma unroll
        for (int dn = 0; dn < 4; dn++) {
            float2 r0; r0.x = o[rt][dn][0] * inv0; r0.y = o[rt][dn][1] * inv0;
            float2 r1; r1.x = o[rt][dn][2] * inv1; r1.y = o[rt][dn][3] * inv1;
            *(float2*)(b0 + dn * 8) = r0;
            *(float2*)(b1 + dn * 8) = r1;
        }
    }
}

// ---------------------------------------------------------------------------
// Kernel 3: projection (unchanged)
// ---------------------------------------------------------------------------
__global__ void __launch_bounds__(256) proj_kernel(const float* __restrict__ proj_w,
                                                   const float* __restrict__ proj_b,
                                                   float* __restrict__ out) {
    __shared__ float w_sh[32 * 196];
    __shared__ float a_sh[64 * 33];

    int blk = blockIdx.x, t = threadIdx.x;
    int tok0 = blk * 64;
    int tokl = (t & 15) * 4;
    int cob  = (t >> 4) * 12;

    u64 acc2[24];
    #pragma unroll
    for (int e = 0; e < 24; e++) acc2[e] = 0ull;

    for (int k0 = 0; k0 < CC; k0 += 32) {
        for (int e = t; e < 2048; e += 256) {
            int tk = e >> 5, kk = e & 31;
            a_sh[tk * 33 + kk] = g_ow[(size_t)(tok0 + tk) * CC + k0 + kk];
        }
        {
            int kk = t & 31;
            for (int co = t >> 5; co < CC; co += 8)
                w_sh[kk * 196 + co] = proj_w[co * CC + k0 + kk];
        }
        __syncthreads();

        #pragma unroll 4
        for (int kk = 0; kk < 32; kk++) {
            u64 ap[4];
            #pragma unroll
            for (int t4 = 0; t4 < 4; t4++) {
                float a = a_sh[(tokl + t4) * 33 + kk];
                ap[t4] = pack2(a, a);
            }
            const ulonglong2* wp = (const ulonglong2*)(w_sh + kk * 196 + cob);
            #pragma unroll
            for (int o2 = 0; o2 < 3; o2++) {
                ulonglong2 wv = wp[o2];
                #pragma unroll
                for (int t4 = 0; t4 < 4; t4++) {
                    acc2[t4 * 6 + o2 * 2 + 0] = ffma2(ap[t4], wv.x, acc2[t4 * 6 + o2 * 2 + 0]);
                    acc2[t4 * 6 + o2 * 2 + 1] = ffma2(ap[t4], wv.y, acc2[t4 * 6 + o2 * 2 + 1]);
                }
            }
        }
        __syncthreads();
    }

    const ulonglong2* bp = (const ulonglong2*)(proj_b + cob);
    ulonglong2 bv0 = bp[0], bv1 = bp[1], bv2 = bp[2];
    u64 bb2[6] = { bv0.x, bv0.y, bv1.x, bv1.y, bv2.x, bv2.y };

    #pragma unroll
    for (int ii = 0; ii < 4; ii++) {
        int gidx = tok0 + tokl + ii;
        int win = gidx >> 8, tt = gidx & 255;
        int b = win / NWB, wr = (win % NWB) / NWSIDE, wc = win % NWSIDE;
        int i = tt >> 4, jj = tt & 15;
        int h = wrapH(wr * WS + i), w = wrapH(wc * WS + jj);
        ulonglong2* op = (ulonglong2*)(out + ((size_t)b * (HH * WW) + h * WW + w) * CC + cob);
        #pragma unroll
        for (int o2 = 0; o2 < 3; o2++) {
            ulonglong2 r;
            r.x = fadd2(acc2[ii * 6 + o2 * 2 + 0], bb2[o2 * 2 + 0]);
            r.y = fadd2(acc2[ii * 6 + o2 * 2 + 1], bb2[o2 * 2 + 1]);
            op[o2] = r;
        }
    }
}

// ---------------------------------------------------------------------------
// Launch.
// ---------------------------------------------------------------------------
extern "C" void kernel_launch(void* const* d_in, const int* in_sizes, int n_in,
                              void* d_out, int out_size) {
    const float* x        = (const float*)d_in[0];
    const float* qkv      = (const float*)d_in[1];
    const float* rpb      = (const float*)d_in[2];
    const float* gscale   = (const float*)d_in[3];
    const float* gsigma   = (const float*)d_in[4];
    const float* proj_w   = (const float*)d_in[5];
    const float* proj_b   = (const float*)d_in[6];
    float* out            = (float*)d_out;

    cudaFuncSetAttribute(attn_kernel, cudaFuncAttributeMaxDynamicSharedMemorySize, SMEM2_BYTES);

    geo_kernel<<<NWIN, 256>>>(x, gsigma);
    attn_kernel<<<dim3(NWIN, NH), 256, SMEM2_BYTES>>>(qkv, rpb, gscale);
    proj_kernel<<<(NWIN * NTOK) / 64, 256>>>(proj_w, proj_b, out);
}

// round 11
// speedup vs baseline: 2.7644x; 1.1463x over previous
#include <cuda_runtime.h>
#include <cuda_bf16.h>
#include <cstdint>

// Problem constants
#define BB 2
#define HH 192
#define WW 192
#define CC 192
#define WS 16
#define SHIFT 8
#define NH 6
#define HD 32
#define NTOK 256          // tokens per window
#define NWSIDE 12         // windows per side
#define NWB 144           // windows per batch
#define NWIN 288          // total windows
#define QK_SCALE 0.17677669529663687f  // 32^-0.5

// ---- mma / ldmatrix helpers ----
__device__ __forceinline__ uint32_t smem_u32(const void* p) {
    return (uint32_t)__cvta_generic_to_shared(p);
}
__device__ __forceinline__ void ldsm_x2(uint32_t& r0, uint32_t& r1, uint32_t addr) {
    asm volatile("ldmatrix.sync.aligned.m8n8.x2.shared.b16 {%0,%1}, [%2];"
                 : "=r"(r0), "=r"(r1) : "r"(addr));
}
__device__ __forceinline__ void ldsm_x2_t(uint32_t& r0, uint32_t& r1, uint32_t addr) {
    asm volatile("ldmatrix.sync.aligned.m8n8.x2.trans.shared.b16 {%0,%1}, [%2];"
                 : "=r"(r0), "=r"(r1) : "r"(addr));
}
__device__ __forceinline__ void ldsm_x4(uint32_t* r, uint32_t addr) {
    asm volatile("ldmatrix.sync.aligned.m8n8.x4.shared.b16 {%0,%1,%2,%3}, [%4];"
                 : "=r"(r[0]), "=r"(r[1]), "=r"(r[2]), "=r"(r[3]) : "r"(addr));
}
__device__ __forceinline__ void mma_bf16(float* c, const uint32_t* a, const uint32_t* b) {
    asm volatile("mma.sync.aligned.m16n8k16.row.col.f32.bf16.bf16.f32 "
                 "{%0,%1,%2,%3},{%4,%5,%6,%7},{%8,%9},{%0,%1,%2,%3};"
                 : "+f"(c[0]), "+f"(c[1]), "+f"(c[2]), "+f"(c[3])
                 : "r"(a[0]), "r"(a[1]), "r"(a[2]), "r"(a[3]), "r"(b[0]), "r"(b[1]));
}
__device__ __forceinline__ uint32_t bf2(float x, float y) {
    __nv_bfloat162 t = __floats2bfloat162_rn(x, y);   // .x = x (low half)
    return *(uint32_t*)&t;
}
__device__ __forceinline__ void split_pack(float x, float y, uint32_t& hi, uint32_t& lo) {
    __nv_bfloat16 hx = __float2bfloat16(x), hy = __float2bfloat16(y);
    __nv_bfloat162 h2 = __halves2bfloat162(hx, hy);
    hi = *(uint32_t*)&h2;
    lo = bf2(x - __bfloat162float(hx), y - __bfloat162float(hy));
}

// Scratch (static __device__ globals)
__device__ float g_cth[NWIN * NTOK];
__device__ float g_ctv[NWIN * NTOK];
__device__ __nv_bfloat16 g_owh[(size_t)NWIN * NTOK * CC];  // attn out hi (28.3MB)
__device__ __nv_bfloat16 g_owl[(size_t)NWIN * NTOK * CC];  // attn out lo
__device__ __nv_bfloat16 g_Wh[CC * CC];                    // proj_w hi
__device__ __nv_bfloat16 g_Wl[CC * CC];                    // proj_w lo

__device__ __forceinline__ int wrapH(int hs) { int h = hs + SHIFT; return (h >= HH) ? h - HH : h; }

// ---------------------------------------------------------------------------
// Kernel 0: split proj_w into bf16 hi/lo (one-time, trivial)
// ---------------------------------------------------------------------------
__global__ void __launch_bounds__(256) wprep_kernel(const float* __restrict__ proj_w) {
    int idx = blockIdx.x * 256 + threadIdx.x;
    if (idx < CC * CC) {
        float v = proj_w[idx];
        __nv_bfloat16 h = __float2bfloat16(v);
        g_Wh[idx] = h;
        g_Wl[idx] = __float2bfloat16(v - __bfloat162float(h));
    }
}

// ---------------------------------------------------------------------------
// Kernel 1: per-window geo cumulative tables cth/ctv (unchanged)
// ---------------------------------------------------------------------------
__global__ void __launch_bounds__(256) geo_kernel(const float* __restrict__ x,
                                                  const float* __restrict__ geo_sigma) {
    int win = blockIdx.x;
    int b = win / NWB, wr = (win % NWB) / NWSIDE, wc = win % NWSIDE;
    int tid = threadIdx.x;

    __shared__ float dh[16][16];
    __shared__ float dv[16][16];

    float sigma = fabsf(geo_sigma[0]);

    for (int p = tid; p < 480; p += 256) {
        int r0, c0, r1, c1; bool isH = (p < 240);
        if (isH) { int r = p / 15, j = p % 15; r0 = r; c0 = j; r1 = r; c1 = j + 1; }
        else     { int pp = p - 240; int i = pp / 16, c = pp % 16; r0 = i; c0 = c; r1 = i + 1; c1 = c; }
        int h0 = wrapH(wr * WS + r0), w0 = wrapH(wc * WS + c0);
        int h1 = wrapH(wr * WS + r1), w1 = wrapH(wc * WS + c1);
        const float* a  = x + ((size_t)((b * HH + h0) * WW + w0)) * CC;
        const float* bb = x + ((size_t)((b * HH + h1) * WW + w1)) * CC;
        float s = 0.f;
        #pragma unroll 4
        for (int ch = 0; ch < CC; ch += 4) {
            float4 av = *(const float4*)(a + ch);
            float4 bv = *(const float4*)(bb + ch);
            s += fabsf(bv.x - av.x) + fabsf(bv.y - av.y) + fabsf(bv.z - av.z) + fabsf(bv.w - av.w);
        }
        if (isH) dh[r0][c0] = s; else dv[r0][c0] = s;
    }
    __syncthreads();

    if (tid < 16) {
        int r = tid; float acc = 0.f;
        g_cth[win * NTOK + r * 16 + 0] = 0.f;
        for (int c = 1; c < 16; c++) {
            acc += 1.f + sigma * dh[r][c - 1];
            g_cth[win * NTOK + r * 16 + c] = acc;
        }
    } else if (tid < 32) {
        int c = tid - 16; float acc = 0.f;
        g_ctv[win * NTOK + 0 * 16 + c] = 0.f;
        for (int r = 1; r < 16; r++) {
            acc += 1.f + sigma * dv[r - 1][c];
            g_ctv[win * NTOK + r * 16 + c] = acc;
        }
    }
}

// ---------------------------------------------------------------------------
// Kernel 2: attention via mma.sync bf16 hi/lo split (unchanged mainloop from R8,
// which measured 513us total / rel_err 5e-6). Output now written as bf16 hi/lo
// so the projection GEMM consumes tensor-ready operands with no conversion.
// ---------------------------------------------------------------------------
#define KV_STRIDE 40
#define SMEM2_BYTES (4 * 256 * KV_STRIDE * 2 + (964 + 256 + 256 + 256) * 4)

__device__ __forceinline__ const float* q_row_ptr(const float* qkv, int b, int wr, int wc,
                                                  int t, int head) {
    int i = t >> 4, j = t & 15;
    int h = wrapH(wr * WS + i), w = wrapH(wc * WS + j);
    return qkv + ((size_t)((b * HH + h) * WW + w)) * (3 * CC) + head * HD;
}

__global__ void __launch_bounds__(256) attn_kernel(const float* __restrict__ qkv,
                                                   const float* __restrict__ rpb_table,
                                                   const float* __restrict__ geo_scale) {
    extern __shared__ char smem_raw[];
    __nv_bfloat16* Kh = (__nv_bfloat16*)smem_raw;              // [256][40]
    __nv_bfloat16* Kl = Kh + 256 * KV_STRIDE;
    __nv_bfloat16* Vh = Kl + 256 * KV_STRIDE;
    __nv_bfloat16* Vl = Vh + 256 * KV_STRIDE;
    float* rpb_sh = (float*)(smem_raw + 4 * 256 * KV_STRIDE * 2);  // [961] pad 964
    float* cth_sh = rpb_sh + 964;
    float* ctv_sh = cth_sh + 256;
    int*   reg_sh = (int*)(ctv_sh + 256);

    int win = blockIdx.x, head = blockIdx.y;
    int b = win / NWB, wr = (win % NWB) / NWSIDE, wc = win % NWSIDE;
    int tid = threadIdx.x;

    // ---- fill K/V hi/lo + tables ----
    {
        int t = tid;
        int i = t >> 4, j = t & 15;
        int hs = wr * WS + i, ws = wc * WS + j;
        int h = wrapH(hs), w = wrapH(ws);
        const float* base = qkv + ((size_t)((b * HH + h) * WW + w)) * (3 * CC) + head * HD;
        const float* kp = base + CC;
        const float* vp = base + 2 * CC;
        #pragma unroll 8
        for (int d = 0; d < 32; d++) {
            float kv = kp[d];
            __nv_bfloat16 khv = __float2bfloat16(kv);
            Kh[t * KV_STRIDE + d] = khv;
            Kl[t * KV_STRIDE + d] = __float2bfloat16(kv - __bfloat162float(khv));
            float vv = vp[d];
            __nv_bfloat16 vhv = __float2bfloat16(vv);
            Vh[t * KV_STRIDE + d] = vhv;
            Vl[t * KV_STRIDE + d] = __float2bfloat16(vv - __bfloat162float(vhv));
        }
        for (int u = tid; u < 961; u += 256) rpb_sh[u] = rpb_table[u * NH + head];
        cth_sh[t] = g_cth[win * NTOK + t];
        ctv_sh[t] = g_ctv[win * NTOK + t];
        int rh  = (hs < HH - WS) ? 0 : ((hs < HH - SHIFT) ? 1 : 2);
        int rw2 = (ws < WW - WS) ? 0 : ((ws < WW - SHIFT) ? 1 : 2);
        reg_sh[t] = rh * 3 + rw2;
    }

    int warp = tid >> 5, lane = tid & 31;
    int g = lane >> 2, t4 = lane & 3;

    // ---- Q fragments straight from gmem (scale folded, hi/lo split) ----
    uint32_t qfh[2][2][4], qfl[2][2][4];
    #pragma unroll
    for (int rt = 0; rt < 2; rt++) {
        int R = warp * 32 + rt * 16;
        const float* p0 = q_row_ptr(qkv, b, wr, wc, R + g, head);
        const float* p1 = q_row_ptr(qkv, b, wr, wc, R + g + 8, head);
        #pragma unroll
        for (int ks = 0; ks < 2; ks++) {
            int kc = ks * 16 + 2 * t4;
            float2 v;
            v = *(const float2*)(p0 + kc);
            split_pack(v.x * QK_SCALE, v.y * QK_SCALE, qfh[rt][ks][0], qfl[rt][ks][0]);
            v = *(const float2*)(p1 + kc);
            split_pack(v.x * QK_SCALE, v.y * QK_SCALE, qfh[rt][ks][1], qfl[rt][ks][1]);
            v = *(const float2*)(p0 + kc + 8);
            split_pack(v.x * QK_SCALE, v.y * QK_SCALE, qfh[rt][ks][2], qfl[rt][ks][2]);
            v = *(const float2*)(p1 + kc + 8);
            split_pack(v.x * QK_SCALE, v.y * QK_SCALE, qfh[rt][ks][3], qfl[rt][ks][3]);
        }
    }
    __syncthreads();

    // ---- per-rt epilogue constants ----
    float gsc = geo_scale[head];
    float cth_q[2][2]; int myreg[2][2];
    #pragma unroll
    for (int rt = 0; rt < 2; rt++) {
        int R = warp * 32 + rt * 16;
        cth_q[rt][0] = cth_sh[R + g];     myreg[rt][0] = reg_sh[R + g];
        cth_q[rt][1] = cth_sh[R + g + 8]; myreg[rt][1] = reg_sh[R + g + 8];
    }

    float o[2][4][4];
    #pragma unroll
    for (int rt = 0; rt < 2; rt++)
        #pragma unroll
        for (int dn = 0; dn < 4; dn++)
            #pragma unroll
            for (int e = 0; e < 4; e++) o[rt][dn][e] = 0.f;
    float lsum[2][2] = {{0.f, 0.f}, {0.f, 0.f}};

    int lrow = lane & 7, lhi = (lane >> 3) & 1;

    #pragma unroll 1
    for (int T = 0; T < 8; T++) {
        int kb = T * 32;

        uint32_t kf_h[4][2][2], kf_l[4][2][2];
        #pragma unroll
        for (int nt = 0; nt < 4; nt++) {
            int row = kb + nt * 8 + lrow;
            #pragma unroll
            for (int ks = 0; ks < 2; ks++) {
                int eoff = ks * 16 + 8 * lhi;
                ldsm_x2(kf_h[nt][ks][0], kf_h[nt][ks][1], smem_u32(&Kh[row * KV_STRIDE + eoff]));
                ldsm_x2(kf_l[nt][ks][0], kf_l[nt][ks][1], smem_u32(&Kl[row * KV_STRIDE + eoff]));
            }
        }
        uint32_t vf_h[4][2][2], vf_l[4][2][2];
        #pragma unroll
        for (int kt = 0; kt < 2; kt++) {
            int key = kb + kt * 16 + lrow + 8 * lhi;
            #pragma unroll
            for (int dn = 0; dn < 4; dn++) {
                ldsm_x2_t(vf_h[dn][kt][0], vf_h[dn][kt][1], smem_u32(&Vh[key * KV_STRIDE + dn * 8]));
                ldsm_x2_t(vf_l[dn][kt][0], vf_l[dn][kt][1], smem_u32(&Vl[key * KV_STRIDE + dn * 8]));
            }
        }

        uint32_t pf_h[2][2][4], pf_l[2][2][4];
        #pragma unroll
        for (int rt = 0; rt < 2; rt++) {
            int R = warp * 32 + rt * 16;
            int rq = warp * 2 + rt;
            #pragma unroll
            for (int nt = 0; nt < 4; nt++) {
                float c[4] = {0.f, 0.f, 0.f, 0.f};
                #pragma unroll
                for (int ks = 0; ks < 2; ks++) {
                    mma_bf16(c, qfh[rt][ks], kf_h[nt][ks]);
                    mma_bf16(c, qfh[rt][ks], kf_l[nt][ks]);
                    mma_bf16(c, qfl[rt][ks], kf_h[nt][ks]);
                }
                int rk = (kb >> 4) + (nt >> 1);
                int rowoff = (rq - rk + 15) * 31 + 15;
                int ck0 = (nt & 1) * 8 + 2 * t4;
                int k0 = kb + nt * 8 + 2 * t4;

                float cthgi0 = cth_sh[R + ck0];
                float ctvgi0 = ctv_sh[R + ck0];
                float ctvk0  = ctv_sh[k0];
                int   mr0    = reg_sh[k0];
                float geo00 = fabsf(cthgi0 - cth_q[rt][0]) + fabsf(ctvk0 - ctvgi0);
                float geo01 = fabsf(cthgi0 - cth_q[rt][1]) + fabsf(ctvk0 - ctvgi0);
                float s0 = fmaf(-gsc, geo00, c[0] + rpb_sh[rowoff + g - ck0])
                         + ((myreg[rt][0] == mr0) ? 0.f : -100.f);
                float s2 = fmaf(-gsc, geo01, c[2] + rpb_sh[rowoff + g + 8 - ck0])
                         + ((myreg[rt][1] == mr0) ? 0.f : -100.f);

                float cthgi1 = cth_sh[R + ck0 + 1];
                float ctvgi1 = ctv_sh[R + ck0 + 1];
                float ctvk1  = ctv_sh[k0 + 1];
                int   mr1    = reg_sh[k0 + 1];
                float geo10 = fabsf(cthgi1 - cth_q[rt][0]) + fabsf(ctvk1 - ctvgi1);
                float geo11 = fabsf(cthgi1 - cth_q[rt][1]) + fabsf(ctvk1 - ctvgi1);
                float s1 = fmaf(-gsc, geo10, c[1] + rpb_sh[rowoff + g - ck0 - 1])
                         + ((myreg[rt][0] == mr1) ? 0.f : -100.f);
                float s3 = fmaf(-gsc, geo11, c[3] + rpb_sh[rowoff + g + 8 - ck0 - 1])
                         + ((myreg[rt][1] == mr1) ? 0.f : -100.f);

                float p0 = __expf(s0), p1 = __expf(s1);
                float p2 = __expf(s2), p3 = __expf(s3);
                lsum[rt][0] += p0 + p1;
                lsum[rt][1] += p2 + p3;

                __nv_bfloat16 h0 = __float2bfloat16(p0), h1 = __float2bfloat16(p1);
                __nv_bfloat16 h2 = __float2bfloat16(p2), h3 = __float2bfloat16(p3);
                int kt = nt >> 1, off = (nt & 1) * 2;
                __nv_bfloat162 hp01 = __halves2bfloat162(h0, h1);
                __nv_bfloat162 hp23 = __halves2bfloat162(h2, h3);
                pf_h[rt][kt][off]     = *(uint32_t*)&hp01;
                pf_h[rt][kt][off + 1] = *(uint32_t*)&hp23;
                pf_l[rt][kt][off]     = bf2(p0 - __bfloat162float(h0), p1 - __bfloat162float(h1));
                pf_l[rt][kt][off + 1] = bf2(p2 - __bfloat162float(h2), p3 - __bfloat162float(h3));
            }
        }

        #pragma unroll
        for (int rt = 0; rt < 2; rt++)
            #pragma unroll
            for (int dn = 0; dn < 4; dn++)
                #pragma unroll
                for (int kt = 0; kt < 2; kt++) {
                    mma_bf16(o[rt][dn], pf_h[rt][kt], vf_h[dn][kt]);
                    mma_bf16(o[rt][dn], pf_h[rt][kt], vf_l[dn][kt]);
                    mma_bf16(o[rt][dn], pf_l[rt][kt], vf_h[dn][kt]);
                }
    }

    #pragma unroll
    for (int rt = 0; rt < 2; rt++)
        #pragma unroll
        for (int r = 0; r < 2; r++) {
            float v = lsum[rt][r];
            v += __shfl_xor_sync(0xFFFFFFFF, v, 1);
            v += __shfl_xor_sync(0xFFFFFFFF, v, 2);
            lsum[rt][r] = v;
        }

    // normalize + store as bf16 hi/lo (tensor-ready for proj)
    #pragma unroll
    for (int rt = 0; rt < 2; rt++) {
        int R = warp * 32 + rt * 16;
        float inv0 = 1.f / lsum[rt][0];
        float inv1 = 1.f / lsum[rt][1];
        size_t i0 = (size_t)win * (NTOK * CC) + (R + g) * CC + head * HD + 2 * t4;
        size_t i1 = (size_t)win * (NTOK * CC) + (R + g + 8) * CC + head * HD + 2 * t4;
        #pragma unroll
        for (int dn = 0; dn < 4; dn++) {
            uint32_t hi, lo;
            split_pack(o[rt][dn][0] * inv0, o[rt][dn][1] * inv0, hi, lo);
            *(uint32_t*)(g_owh + i0 + dn * 8) = hi;
            *(uint32_t*)(g_owl + i0 + dn * 8) = lo;
            split_pack(o[rt][dn][2] * inv1, o[rt][dn][3] * inv1, hi, lo);
            *(uint32_t*)(g_owh + i1 + dn * 8) = hi;
            *(uint32_t*)(g_owl + i1 + dn * 8) = lo;
        }
    }
}

// ---------------------------------------------------------------------------
// Kernel 3: projection via mma.sync bf16 hi/lo split.
// Block = 64 tokens x 192 outs; 8 warps as 4(m) x 2(n): warp = m16 x n96.
// K loop: 12 chunks of 16; W chunk staged per iter (L2-resident hi/lo tables).
// Strides: A 200 halfs (rows i*100 mod 32 distinct), W 24 halfs (i*12 mod 32
// distinct) -> conflict-free ldmatrix.
// ---------------------------------------------------------------------------
#define AST 200
#define WST 24
#define SMEM3_BYTES ((2 * 64 * AST + 2 * 192 * WST) * 2)

__global__ void __launch_bounds__(256) proj_kernel(const float* __restrict__ proj_b,
                                                   float* __restrict__ out) {
    extern __shared__ char smem3[];
    __nv_bfloat16* Ah = (__nv_bfloat16*)smem3;          // [64][AST]
    __nv_bfloat16* Al = Ah + 64 * AST;
    __nv_bfloat16* Ws_h = Al + 64 * AST;                // [192][WST]
    __nv_bfloat16* Ws_l = Ws_h + 192 * WST;

    int t = threadIdx.x;
    int tok0 = blockIdx.x * 64;

    // Stage A tile (bf16 hi/lo straight from attn output)
    for (int e = t; e < 64 * 96; e += 256) {
        int row = e / 96, c2 = (e % 96) * 2;
        size_t gidx = (size_t)(tok0 + row) * CC + c2;
        *(uint32_t*)&Ah[row * AST + c2] = *(const uint32_t*)(g_owh + gidx);
        *(uint32_t*)&Al[row * AST + c2] = *(const uint32_t*)(g_owl + gidx);
    }

    int warp = t >> 5, lane = t & 31;
    int mw = warp & 3, nw = warp >> 2;
    int g = lane >> 2, t4 = lane & 3;
    int lg = lane >> 3;

    float acc[12][4];
    #pragma unroll
    for (int nt = 0; nt < 12; nt++)
        #pragma unroll
        for (int e = 0; e < 4; e++) acc[nt][e] = 0.f;

    // ldmatrix lane->address precompute
    int a_row = mw * 16 + (lane & 7) + (lg & 1) * 8;   // A: g0=r0-7@k0 g1=r8-15@k0 g2=r0-7@k8 g3=r8-15@k8
    int a_col = (lg >> 1) * 8;
    int w_lrow = (lane & 7) + (lg >> 1) * 8;           // W: g0=n0-7@k0 g1=n0-7@k8 g2=n8-15@k0 g3=n8-15@k8
    int w_col = (lg & 1) * 8;

    #pragma unroll 1
    for (int kc = 0; kc < 12; kc++) {
        __syncthreads();   // A stores (first iter) / previous-iter W readers done
        // Stage W chunk: [192 outs][16 k] hi+lo
        for (int e = t; e < 1536; e += 256) {
            int row = e >> 3, c2 = (e & 7) * 2;
            *(uint32_t*)&Ws_h[row * WST + c2] = *(const uint32_t*)(g_Wh + row * CC + kc * 16 + c2);
            *(uint32_t*)&Ws_l[row * WST + c2] = *(const uint32_t*)(g_Wl + row * CC + kc * 16 + c2);
        }
        __syncthreads();

        uint32_t af_h[4], af_l[4];
        ldsm_x4(af_h, smem_u32(&Ah[a_row * AST + kc * 16 + a_col]));
        ldsm_x4(af_l, smem_u32(&Al[a_row * AST + kc * 16 + a_col]));

        uint32_t wf_h[12][2], wf_l[12][2];
        #pragma unroll
        for (int nt2 = 0; nt2 < 6; nt2++) {
            int nbase = nw * 96 + nt2 * 16;
            uint32_t r4[4];
            ldsm_x4(r4, smem_u32(&Ws_h[(nbase + w_lrow) * WST + w_col]));
            wf_h[2 * nt2][0] = r4[0]; wf_h[2 * nt2][1] = r4[1];
            wf_h[2 * nt2 + 1][0] = r4[2]; wf_h[2 * nt2 + 1][1] = r4[3];
            ldsm_x4(r4, smem_u32(&Ws_l[(nbase + w_lrow) * WST + w_col]));
            wf_l[2 * nt2][0] = r4[0]; wf_l[2 * nt2][1] = r4[1];
            wf_l[2 * nt2 + 1][0] = r4[2]; wf_l[2 * nt2 + 1][1] = r4[3];
        }

        #pragma unroll
        for (int nt = 0; nt < 12; nt++) {
            mma_bf16(acc[nt], af_h, wf_h[nt]);
            mma_bf16(acc[nt], af_h, wf_l[nt]);
            mma_bf16(acc[nt], af_l, wf_h[nt]);
        }
    }

    // Epilogue: bias + window-reverse + roll-back scatter
    #pragma unroll
    for (int half = 0; half < 2; half++) {
        int tok = tok0 + mw * 16 + g + half * 8;
        int win = tok >> 8, tt = tok & 255;
        int b = win / NWB, wr = (win % NWB) / NWSIDE, wc = win % NWSIDE;
        int i = tt >> 4, jj = tt & 15;
        int h = wrapH(wr * WS + i), w = wrapH(wc * WS + jj);
        float* op = out + ((size_t)b * (HH * WW) + h * WW + w) * CC;
        #pragma unroll
        for (int nt = 0; nt < 12; nt++) {
            int co = nw * 96 + nt * 8 + 2 * t4;
            float2 r;
            r.x = acc[nt][2 * half + 0] + __ldg(proj_b + co);
            r.y = acc[nt][2 * half + 1] + __ldg(proj_b + co + 1);
            *(float2*)(op + co) = r;
        }
    }
}

// ---------------------------------------------------------------------------
// Launch.
// ---------------------------------------------------------------------------
extern "C" void kernel_launch(void* const* d_in, const int* in_sizes, int n_in,
                              void* d_out, int out_size) {
    const float* x        = (const float*)d_in[0];
    const float* qkv      = (const float*)d_in[1];
    const float* rpb      = (const float*)d_in[2];
    const float* gscale   = (const float*)d_in[3];
    const float* gsigma   = (const float*)d_in[4];
    const float* proj_w   = (const float*)d_in[5];
    const float* proj_b   = (const float*)d_in[6];
    float* out            = (float*)d_out;

    cudaFuncSetAttribute(attn_kernel, cudaFuncAttributeMaxDynamicSharedMemorySize, SMEM2_BYTES);
    cudaFuncSetAttribute(proj_kernel, cudaFuncAttributeMaxDynamicSharedMemorySize, SMEM3_BYTES);

    wprep_kernel<<<(CC * CC + 255) / 256, 256>>>(proj_w);
    geo_kernel<<<NWIN, 256>>>(x, gsigma);
    attn_kernel<<<dim3(NWIN, NH), 256, SMEM2_BYTES>>>(qkv, rpb, gscale);
    proj_kernel<<<(NWIN * NTOK) / 64, 256, SMEM3_BYTES>>>(proj_b, out);
}